// round 14
// baseline (speedup 1.0000x reference)
#include <cuda_runtime.h>
#include <cuda_bf16.h>
#include <cuda_fp16.h>
#include <cstdint>
#include <math.h>

#define S_SYS 32
#define N_ATOM 512
#define F_DIM 256
#define R_EXCL 5.0f

// Scratch (__device__ globals; allocation-free rule).
__device__ __align__(16) uint16_t g_q16[(size_t)S_SYS * F_DIM * N_ATOM]; // 8 MB  q^T fp16
__device__ __align__(16) float    g_q32[(size_t)S_SYS * F_DIM * N_ATOM]; // 16 MB q^T fp32

// ---------------------------------------------------------------------------
// helpers
// ---------------------------------------------------------------------------
__device__ __forceinline__ uint32_t smem_u32(const void* p) {
    uint32_t a;
    asm("{ .reg .u64 t; cvta.to.shared.u64 t, %1; cvt.u32.u64 %0, t; }" : "=r"(a) : "l"(p));
    return a;
}
__device__ __forceinline__ uint32_t pack_bf16(float lo_elem, float hi_elem) {
    uint32_t r;
    asm("cvt.rn.bf16x2.f32 %0, %1, %2;" : "=r"(r) : "f"(hi_elem), "f"(lo_elem));
    return r;
}
__device__ __forceinline__ float bf_lo(uint32_t p) { return __uint_as_float(p << 16); }
__device__ __forceinline__ float bf_hi(uint32_t p) { return __uint_as_float(p & 0xFFFF0000u); }

__device__ __forceinline__ void mma_bf16(float* c, const uint32_t* a, uint32_t b0, uint32_t b1) {
    asm volatile(
        "mma.sync.aligned.m16n8k16.row.col.f32.bf16.bf16.f32 "
        "{%0,%1,%2,%3}, {%4,%5,%6,%7}, {%8,%9}, {%0,%1,%2,%3};"
        : "+f"(c[0]), "+f"(c[1]), "+f"(c[2]), "+f"(c[3])
        : "r"(a[0]), "r"(a[1]), "r"(a[2]), "r"(a[3]), "r"(b0), "r"(b1));
}
__device__ __forceinline__ void mma_f16(float* c, const uint32_t* a, uint32_t b0, uint32_t b1) {
    asm volatile(
        "mma.sync.aligned.m16n8k16.row.col.f32.f16.f16.f32 "
        "{%0,%1,%2,%3}, {%4,%5,%6,%7}, {%8,%9}, {%0,%1,%2,%3};"
        : "+f"(c[0]), "+f"(c[1]), "+f"(c[2]), "+f"(c[3])
        : "r"(a[0]), "r"(a[1]), "r"(a[2]), "r"(a[3]), "r"(b0), "r"(b1));
}
__device__ __forceinline__ void ldsm4(uint32_t* r, uint32_t addr) {
    asm volatile("ldmatrix.sync.aligned.m8n8.x4.shared.b16 {%0,%1,%2,%3}, [%4];"
                 : "=r"(r[0]), "=r"(r[1]), "=r"(r[2]), "=r"(r[3]) : "r"(addr));
}
#define CP_ASYNC16(dst, src) \
    asm volatile("cp.async.cg.shared.global [%0], [%1], 16;" :: "r"(dst), "l"(src))
#define CP_COMMIT() asm volatile("cp.async.commit_group;" ::: "memory")
#define CP_WAIT(n)  asm volatile("cp.async.wait_group %0;" :: "n"(n) : "memory")
// named barriers (id 0 reserved for __syncthreads)
#define BAR_SYNC(id, cnt)   asm volatile("bar.sync %0, %1;"   :: "r"(id), "n"(cnt) : "memory")
#define BAR_ARRIVE(id, cnt) asm volatile("bar.arrive %0, %1;" :: "r"(id), "n"(cnt) : "memory")

// ===========================================================================
// GEMM1 (unchanged from R12): qT = W @ feat^T + b, 3-term bf16; fp16+fp32 out
// ===========================================================================
#define G1_RAWA(st) ((st) * 32768)
#define G1_RAWB(st) ((st) * 32768 + 16384)
#define G1_AH 65536
#define G1_AL 75776
#define G1_BH 86016
#define G1_BL 96256
#define G1_SMEM 106496

__device__ __forceinline__ void gemm1_step(
    uint32_t sb, const uint32_t arow[2], const uint32_t brow[4], float c[2][8][4])
{
    #pragma unroll
    for (int ks = 0; ks < 2; ++ks) {
        const uint32_t col = (uint32_t)(ks * 32);
        uint32_t ah[2][4], al[2][4], bh[4][4];
        #pragma unroll
        for (int mt = 0; mt < 2; ++mt) ldsm4(ah[mt], sb + G1_AH + arow[mt] + col);
        #pragma unroll
        for (int mt = 0; mt < 2; ++mt) ldsm4(al[mt], sb + G1_AL + arow[mt] + col);
        #pragma unroll
        for (int np = 0; np < 4; ++np) ldsm4(bh[np], sb + G1_BH + brow[np] + col);
        #pragma unroll
        for (int mt = 0; mt < 2; ++mt)
            #pragma unroll
            for (int nt = 0; nt < 8; ++nt)
                mma_bf16(c[mt][nt], ah[mt], bh[nt >> 1][nt & 1], bh[nt >> 1][(nt & 1) + 2]);
        #pragma unroll
        for (int mt = 0; mt < 2; ++mt)
            #pragma unroll
            for (int nt = 0; nt < 8; ++nt)
                mma_bf16(c[mt][nt], al[mt], bh[nt >> 1][nt & 1], bh[nt >> 1][(nt & 1) + 2]);
        uint32_t bl[4][4];
        #pragma unroll
        for (int np = 0; np < 4; ++np) ldsm4(bl[np], sb + G1_BL + brow[np] + col);
        #pragma unroll
        for (int mt = 0; mt < 2; ++mt)
            #pragma unroll
            for (int nt = 0; nt < 8; ++nt)
                mma_bf16(c[mt][nt], ah[mt], bl[nt >> 1][nt & 1], bl[nt >> 1][(nt & 1) + 2]);
    }
}

__global__ __launch_bounds__(256, 2) void gemm1_mma(
    const float* __restrict__ W, const float* __restrict__ feat,
    const float* __restrict__ bias,
    uint16_t* __restrict__ q16, float* __restrict__ q32)
{
    extern __shared__ char sm[];
    const int t = threadIdx.x, lane = t & 31, w = t >> 5;
    const int wm = (w & 3) * 32, wn = (w >> 2) * 64;
    const int aB = blockIdx.x * 128, fB = blockIdx.y * 128;
    const uint32_t sb = smem_u32(sm);

    const char* Ag = (const char*)(W + (size_t)fB * F_DIM);
    const char* Bg = (const char*)(feat + (size_t)aB * F_DIM);

    float c[2][8][4] = {};
    const int mrow = (lane & 7) + ((lane >> 3) & 1) * 8;
    const int kb   = (lane >> 4) * 16;
    uint32_t arow[2], brow[4];
    #pragma unroll
    for (int mt = 0; mt < 2; ++mt) arow[mt] = (uint32_t)((wm + mt * 16 + mrow) * 80 + kb);
    #pragma unroll
    for (int np = 0; np < 4; ++np) brow[np] = (uint32_t)((wn + np * 16 + mrow) * 80 + kb);

    auto load_raw = [&](int ch, int st) {
        #pragma unroll
        for (int j = 0; j < 8; ++j) {
            int u = t + j * 256;
            if (u < 1024) {
                int row = u >> 3, sg = u & 7;
                CP_ASYNC16(sb + G1_RAWA(st) + (uint32_t)(row * 128 + sg * 16),
                           Ag + (size_t)row * 1024 + ch * 128 + sg * 16);
            } else {
                int u2 = u - 1024, row = u2 >> 3, sg = u2 & 7;
                CP_ASYNC16(sb + G1_RAWB(st) + (uint32_t)(row * 128 + sg * 16),
                           Bg + (size_t)row * 1024 + ch * 128 + sg * 16);
            }
        }
        CP_COMMIT();
    };

    load_raw(0, 0);

    for (int ch = 0; ch < 8; ++ch) {
        if (ch + 1 < 8) {
            load_raw(ch + 1, (ch + 1) & 1);
            CP_WAIT(1);
        } else {
            CP_WAIT(0);
        }
        __syncthreads();

        {
            const char* rawA = sm + G1_RAWA(ch & 1);
            const char* rawB = sm + G1_RAWB(ch & 1);
            #pragma unroll
            for (int j = 0; j < 8; ++j) {
                int u = t + j * 256;
                const char* src;
                uint32_t dhi, dlo;
                int row, kq;
                if (u < 1024) {
                    row = u >> 3; kq = u & 7;
                    src = rawA + row * 128 + kq * 16;
                    dhi = (uint32_t)G1_AH; dlo = (uint32_t)G1_AL;
                } else {
                    int u2 = u - 1024; row = u2 >> 3; kq = u2 & 7;
                    src = rawB + row * 128 + kq * 16;
                    dhi = (uint32_t)G1_BH; dlo = (uint32_t)G1_BL;
                }
                float4 x = *(const float4*)src;
                uint32_t h01 = pack_bf16(x.x, x.y);
                uint32_t h23 = pack_bf16(x.z, x.w);
                uint32_t l01 = pack_bf16(x.x - bf_lo(h01), x.y - bf_hi(h01));
                uint32_t l23 = pack_bf16(x.z - bf_lo(h23), x.w - bf_hi(h23));
                uint32_t off = (uint32_t)(row * 80 + kq * 8);
                *(uint2*)(sm + dhi + off) = make_uint2(h01, h23);
                *(uint2*)(sm + dlo + off) = make_uint2(l01, l23);
            }
        }
        __syncthreads();

        gemm1_step(sb, arow, brow, c);
    }

    const int sID = blockIdx.x >> 2;
    const int aLoc0 = (blockIdx.x & 3) * 128;
    uint16_t* qh16 = q16 + (size_t)sID * F_DIM * N_ATOM;
    float*    qh32 = q32 + (size_t)sID * F_DIM * N_ATOM;
    #pragma unroll
    for (int mt = 0; mt < 2; ++mt) {
        #pragma unroll
        for (int nt = 0; nt < 8; ++nt) {
            const int fg = fB + wm + mt * 16 + (lane >> 2);
            const int ag = aLoc0 + wn + nt * 8 + (lane & 3) * 2;
            float* cf = c[mt][nt];
            float bv0 = bias[fg], bv1 = bias[fg + 8];
            float y0 = cf[0] + bv0, y1 = cf[1] + bv0;
            float y2 = cf[2] + bv1, y3 = cf[3] + bv1;
            *(float2*)(qh32 + (size_t)fg * N_ATOM + ag) = make_float2(y0, y1);
            *(float2*)(qh32 + (size_t)(fg + 8) * N_ATOM + ag) = make_float2(y2, y3);
            __half2 p01 = __floats2half2_rn(y0, y1);
            __half2 p23 = __floats2half2_rn(y2, y3);
            *(__half2*)(qh16 + (size_t)fg * N_ATOM + ag) = p01;
            *(__half2*)(qh16 + (size_t)(fg + 8) * N_ATOM + ag) = p23;
        }
    }
}

// ===========================================================================
// GEMM2 warp-specialized: out[s,m,f] = 0.5*(sum_j v(m,j) q[j,f])*q[m,f]
// 384 threads: warps 0-7 consumers (MMA, warp tile 32x64, BM=64 BN=256),
// warps 8-11 producers (v fp16 on-the-fly + q cp.async).
// V: 2 stages (named barriers full=1,2 / empty=3,4). Q: 4-stage ring,
// loads issued 2 chunks ahead (wait_group 2). BK=32, 16 chunks.
// smem: pos@0(6K) | V @6144 (2x5120) | Q @16384 (4x20480) = 98304
// ===========================================================================
#define G2_VS(st) (6144 + (st) * 5120)
#define G2_QS(st) (16384 + (st) * 20480)
#define G2_SMEM 98304

__device__ __forceinline__ void gemm2_step(
    uint32_t vbase, uint32_t qbase,
    const uint32_t arow[2], const uint32_t brow[4], float c[2][8][4])
{
    #pragma unroll
    for (int ks = 0; ks < 2; ++ks) {
        const uint32_t col = (uint32_t)(ks * 32);
        uint32_t ah[2][4], bh[4][4];
        #pragma unroll
        for (int mt = 0; mt < 2; ++mt) ldsm4(ah[mt], vbase + arow[mt] + col);
        #pragma unroll
        for (int np = 0; np < 4; ++np) ldsm4(bh[np], qbase + brow[np] + col);
        #pragma unroll
        for (int mt = 0; mt < 2; ++mt)
            #pragma unroll
            for (int nt = 0; nt < 8; ++nt)
                mma_f16(c[mt][nt], ah[mt], bh[nt >> 1][nt & 1], bh[nt >> 1][(nt & 1) + 2]);
    }
}

__global__ __launch_bounds__(384, 1) void gemm2_ws(
    const float* __restrict__ pos,
    const uint16_t* __restrict__ q16, const float* __restrict__ q32,
    float* __restrict__ out)
{
    extern __shared__ char sm[];
    const int t = threadIdx.x, lane = t & 31, w = t >> 5;
    const int m0 = blockIdx.x * 64, s = blockIdx.y;
    const uint32_t sb = smem_u32(sm);

    float* sx = (float*)(sm);
    float* sy = (float*)(sm + 2048);
    float* sz = (float*)(sm + 4096);

    // stage all positions of system s
    const float* ps = pos + (size_t)s * N_ATOM * 3;
    for (int j = t; j < N_ATOM; j += 384) {
        float3 p = *(const float3*)(ps + j * 3);
        sx[j] = p.x; sy[j] = p.y; sz[j] = p.z;
    }

    const char* Bq = (const char*)(q16 + (size_t)s * F_DIM * N_ATOM);  // 1024B row stride

    if (w >= 8) {
        // -------- producers (warps 8-11, 128 threads) --------
        const int pt = t - 256;               // 0..127
        // q loader: 256 rows x 64B = 1024 x 16B, 8 per thread
        auto load_q = [&](int ch, int st) {
            #pragma unroll
            for (int j = 0; j < 8; ++j) {
                int u = pt + j * 128;
                int row = u >> 2, sg = u & 3;
                CP_ASYNC16(sb + (uint32_t)(G2_QS(st) + row * 80 + sg * 16),
                           Bq + (size_t)row * 1024 + ch * 64 + sg * 16);
            }
            CP_COMMIT();
        };
        // issue q0, q1 before positions are even needed
        load_q(0, 0);
        load_q(1, 1);
        __syncthreads();   // positions staged

        const int irow = pt >> 1;             // 0..63
        const int jh   = (pt & 1) * 16;       // j-half within 32-chunk
        const int ig   = m0 + irow;
        const float xi = sx[ig], yi = sy[ig], zi = sz[ig];
        const float cc = 3.14159265358979323846f / R_EXCL;

        for (int ch = 0; ch < 16; ++ch) {
            const int vst = ch & 1;
            if (ch >= 2) BAR_SYNC(3 + vst, 384);        // wait empty (consumer done ch-2)
            if (ch + 2 < 16) load_q(ch + 2, (ch + 2) & 3);
            // produce v[ch]: 16 evals -> 2x uint4 fp16
            {
                const int jbase = ch * 32 + jh;
                __half2 hq[8];
                #pragma unroll
                for (int p = 0; p < 8; ++p) {
                    float vv[2];
                    #pragma unroll
                    for (int e = 0; e < 2; ++e) {
                        int j = jbase + p * 2 + e;
                        float dx = xi - sx[j], dy = yi - sy[j], dz = zi - sz[j];
                        float d2 = fmaf(dx, dx, fmaf(dy, dy, dz * dz));
                        float val = 0.0f;
                        if (j != ig) {
                            float inv = rsqrtf(d2);
                            float d = d2 * inv;
                            float fcut = (d < R_EXCL) ? 0.5f * (1.0f + __cosf(cc * d)) : 0.0f;
                            val = (1.0f - fcut) * inv;
                        }
                        vv[e] = val;
                    }
                    hq[p] = __floats2half2_rn(vv[0], vv[1]);
                }
                uint32_t off = (uint32_t)(G2_VS(vst) + irow * 80 + jh * 2);
                *(uint4*)(sm + off)      = ((uint4*)hq)[0];
                *(uint4*)(sm + off + 16) = ((uint4*)hq)[1];
            }
            if (ch <= 13)      CP_WAIT(2);   // q[ch] landed
            else if (ch == 14) CP_WAIT(1);
            else               CP_WAIT(0);
            BAR_ARRIVE(1 + vst, 384);                  // signal full
        }
        __syncthreads();
    } else {
        // -------- consumers (warps 0-7, 256 threads) --------
        const int wm = (w & 1) * 32, wn = (w >> 1) * 64;
        float c[2][8][4] = {};
        const int mrow = (lane & 7) + ((lane >> 3) & 1) * 8;
        const int kb   = (lane >> 4) * 16;
        uint32_t arow[2], brow[4];
        #pragma unroll
        for (int mt = 0; mt < 2; ++mt) arow[mt] = (uint32_t)((wm + mt * 16 + mrow) * 80 + kb);
        #pragma unroll
        for (int np = 0; np < 4; ++np) brow[np] = (uint32_t)((wn + np * 16 + mrow) * 80 + kb);

        __syncthreads();   // positions staged (match producer barrier 0)

        for (int ch = 0; ch < 16; ++ch) {
            const int vst = ch & 1;
            BAR_SYNC(1 + vst, 384);                    // wait full
            gemm2_step(sb + (uint32_t)G2_VS(vst), sb + (uint32_t)G2_QS(ch & 3),
                       arow, brow, c);
            BAR_ARRIVE(3 + vst, 384);                  // signal empty
        }
        __syncthreads();

        // epilogue part 2 happens below after the shared staging sync
        // (we fall through; sq staging is done by ALL threads)
        // store accumulators after staging barrier:
        // (sq layout [256 f][64 m], stride 68 floats)
        // -- staging loop is below, shared with producers --
        // mark consumer role via registers still live (c[][][]).
        // NOTE: control merges at the staging loop.
        // write-out occurs in the 'if (w < 8)' block after the sync below.
        // (structure kept linear for the compiler)
        float* sq = (float*)sm;
        const float* Q32 = q32 + (size_t)s * F_DIM * N_ATOM;
        for (int u = t; u < 4096; u += 384) {          // consumers' share
            int row = u >> 4, un = u & 15;
            float4 x = *(const float4*)(Q32 + (size_t)row * N_ATOM + m0 + un * 4);
            *(float4*)(sq + row * 68 + un * 4) = x;
        }
        __syncthreads();

        float* outB = out + ((size_t)(s * N_ATOM) + m0) * F_DIM;
        #pragma unroll
        for (int mt = 0; mt < 2; ++mt) {
            #pragma unroll
            for (int nt = 0; nt < 8; ++nt) {
                const int ml = wm + mt * 16 + (lane >> 2);
                const int fg = wn + nt * 8 + (lane & 3) * 2;
                float* cf = c[mt][nt];
                float q00 = sq[fg * 68 + ml], q01 = sq[(fg + 1) * 68 + ml];
                float2 o0 = make_float2(0.5f * cf[0] * q00, 0.5f * cf[1] * q01);
                *(float2*)(outB + (size_t)ml * F_DIM + fg) = o0;
                float q10 = sq[fg * 68 + ml + 8], q11 = sq[(fg + 1) * 68 + ml + 8];
                float2 o1 = make_float2(0.5f * cf[2] * q10, 0.5f * cf[3] * q11);
                *(float2*)(outB + (size_t)(ml + 8) * F_DIM + fg) = o1;
            }
        }
        return;
    }

    // producers: participate in epilogue staging + its barrier
    {
        float* sq = (float*)sm;
        const float* Q32 = q32 + (size_t)s * F_DIM * N_ATOM;
        for (int u = t; u < 4096; u += 384) {
            int row = u >> 4, un = u & 15;
            float4 x = *(const float4*)(Q32 + (size_t)row * N_ATOM + m0 + un * 4);
            *(float4*)(sq + row * 68 + un * 4) = x;
        }
        __syncthreads();
    }
}

// ---------------------------------------------------------------------------
extern "C" void kernel_launch(void* const* d_in, const int* in_sizes, int n_in,
                              void* d_out, int out_size)
{
    const float* positions = (const float*)d_in[0]; // [32, 512, 3]
    const float* features  = (const float*)d_in[1]; // [16384, 256]
    const float* W         = (const float*)d_in[2]; // [256, 256]
    const float* b         = (const float*)d_in[3]; // [256]
    float* out             = (float*)d_out;         // [16384, 256]

    uint16_t* q16; float* q32;
    cudaGetSymbolAddress((void**)&q16, g_q16);
    cudaGetSymbolAddress((void**)&q32, g_q32);

    cudaFuncSetAttribute(gemm1_mma, cudaFuncAttributeMaxDynamicSharedMemorySize, G1_SMEM);
    cudaFuncSetAttribute(gemm2_ws, cudaFuncAttributeMaxDynamicSharedMemorySize, G2_SMEM);

    // q^T = W @ feat^T + b  (3-term bf16 -> fp16 + fp32 outputs)
    gemm1_mma<<<dim3(128, 2), 256, G1_SMEM>>>(W, features, b, q16, q32);
    // out = 0.5 * (v @ q) * q  — warp-specialized producer/consumer
    gemm2_ws<<<dim3(8, 32), 384, G2_SMEM>>>(positions, q16, q32, out);
}

// round 15
// speedup vs baseline: 2.0322x; 2.0322x over previous
#include <cuda_runtime.h>
#include <cuda_bf16.h>
#include <cuda_fp16.h>
#include <cstdint>
#include <math.h>

#define S_SYS 32
#define N_ATOM 512
#define F_DIM 256
#define R_EXCL 5.0f

// Scratch (__device__ globals; allocation-free rule).
__device__ __align__(16) uint16_t g_q16[(size_t)S_SYS * F_DIM * N_ATOM]; // 8 MB q^T fp16

// ---------------------------------------------------------------------------
// helpers
// ---------------------------------------------------------------------------
__device__ __forceinline__ uint32_t smem_u32(const void* p) {
    uint32_t a;
    asm("{ .reg .u64 t; cvta.to.shared.u64 t, %1; cvt.u32.u64 %0, t; }" : "=r"(a) : "l"(p));
    return a;
}
__device__ __forceinline__ void mma_f16(float* c, const uint32_t* a, uint32_t b0, uint32_t b1) {
    asm volatile(
        "mma.sync.aligned.m16n8k16.row.col.f32.f16.f16.f32 "
        "{%0,%1,%2,%3}, {%4,%5,%6,%7}, {%8,%9}, {%0,%1,%2,%3};"
        : "+f"(c[0]), "+f"(c[1]), "+f"(c[2]), "+f"(c[3])
        : "r"(a[0]), "r"(a[1]), "r"(a[2]), "r"(a[3]), "r"(b0), "r"(b1));
}
__device__ __forceinline__ void ldsm4(uint32_t* r, uint32_t addr) {
    asm volatile("ldmatrix.sync.aligned.m8n8.x4.shared.b16 {%0,%1,%2,%3}, [%4];"
                 : "=r"(r[0]), "=r"(r[1]), "=r"(r[2]), "=r"(r[3]) : "r"(addr));
}
#define CP_ASYNC16(dst, src) \
    asm volatile("cp.async.cg.shared.global [%0], [%1], 16;" :: "r"(dst), "l"(src))
#define CP_COMMIT() asm volatile("cp.async.commit_group;" ::: "memory")
#define CP_WAIT(n)  asm volatile("cp.async.wait_group %0;" :: "n"(n) : "memory")

// ===========================================================================
// GEMM1: qT[s][f][a] = sum_k W[f,k]*feat[a,k] + b[f]  (single fp16 -> q16)
// BM(f)=128, BN(atom)=128, BK=32, 256 threads, warp tile 32x64 (4f x 2a warps)
// grid (128 atom-tiles, 2 f-tiles) = 256 CTAs, 2 CTAs/SM.
// smem: raw 2 stages x (A 16K + B 16K) | fp16 tiles AH,BH 2 x 10240 = 86016
// ===========================================================================
#define G1_RAWA(st) ((st) * 32768)
#define G1_RAWB(st) ((st) * 32768 + 16384)
#define G1_AH 65536
#define G1_BH 75776
#define G1_SMEM 86016

__global__ __launch_bounds__(256, 2) void gemm1_mma(
    const float* __restrict__ W, const float* __restrict__ feat,
    const float* __restrict__ bias,
    uint16_t* __restrict__ q16)
{
    extern __shared__ char sm[];
    const int t = threadIdx.x, lane = t & 31, w = t >> 5;
    const int wm = (w & 3) * 32, wn = (w >> 2) * 64;
    const int aB = blockIdx.x * 128, fB = blockIdx.y * 128;
    const uint32_t sb = smem_u32(sm);

    const char* Ag = (const char*)(W + (size_t)fB * F_DIM);     // 128 rows, 1024B stride
    const char* Bg = (const char*)(feat + (size_t)aB * F_DIM);  // 128 rows, 1024B stride

    float c[2][8][4] = {};
    const int mrow = (lane & 7) + ((lane >> 3) & 1) * 8;
    const int kb   = (lane >> 4) * 16;
    uint32_t arow[2], brow[4];
    #pragma unroll
    for (int mt = 0; mt < 2; ++mt) arow[mt] = (uint32_t)((wm + mt * 16 + mrow) * 80 + kb);
    #pragma unroll
    for (int np = 0; np < 4; ++np) brow[np] = (uint32_t)((wn + np * 16 + mrow) * 80 + kb);

    // raw loader: 2048 float4/chunk -> 8 per thread (u<1024: A, else B)
    auto load_raw = [&](int ch, int st) {
        #pragma unroll
        for (int j = 0; j < 8; ++j) {
            int u = t + j * 256;
            if (u < 1024) {
                int row = u >> 3, sg = u & 7;
                CP_ASYNC16(sb + G1_RAWA(st) + (uint32_t)(row * 128 + sg * 16),
                           Ag + (size_t)row * 1024 + ch * 128 + sg * 16);
            } else {
                int u2 = u - 1024, row = u2 >> 3, sg = u2 & 7;
                CP_ASYNC16(sb + G1_RAWB(st) + (uint32_t)(row * 128 + sg * 16),
                           Bg + (size_t)row * 1024 + ch * 128 + sg * 16);
            }
        }
        CP_COMMIT();
    };

    load_raw(0, 0);

    for (int ch = 0; ch < 8; ++ch) {
        if (ch + 1 < 8) {
            load_raw(ch + 1, (ch + 1) & 1);
            CP_WAIT(1);
        } else {
            CP_WAIT(0);
        }
        __syncthreads();   // raw[ch] visible; fp16 tiles free (prev MMA done)

        // convert raw fp32 -> single fp16 tiles (8 float4 per thread)
        {
            const char* rawA = sm + G1_RAWA(ch & 1);
            const char* rawB = sm + G1_RAWB(ch & 1);
            #pragma unroll
            for (int j = 0; j < 8; ++j) {
                int u = t + j * 256;
                const char* src;
                uint32_t dst;
                int row, kq;
                if (u < 1024) {
                    row = u >> 3; kq = u & 7;
                    src = rawA + row * 128 + kq * 16;
                    dst = (uint32_t)G1_AH;
                } else {
                    int u2 = u - 1024; row = u2 >> 3; kq = u2 & 7;
                    src = rawB + row * 128 + kq * 16;
                    dst = (uint32_t)G1_BH;
                }
                float4 x = *(const float4*)src;
                __half2 h01 = __floats2half2_rn(x.x, x.y);
                __half2 h23 = __floats2half2_rn(x.z, x.w);
                uint32_t off = (uint32_t)(row * 80 + kq * 8);
                *(uint2*)(sm + dst + off) =
                    make_uint2(*(uint32_t*)&h01, *(uint32_t*)&h23);
            }
        }
        __syncthreads();

        // single fp16 MMA group
        #pragma unroll
        for (int ks = 0; ks < 2; ++ks) {
            const uint32_t col = (uint32_t)(ks * 32);
            uint32_t ah[2][4], bh[4][4];
            #pragma unroll
            for (int mt = 0; mt < 2; ++mt) ldsm4(ah[mt], sb + G1_AH + arow[mt] + col);
            #pragma unroll
            for (int np = 0; np < 4; ++np) ldsm4(bh[np], sb + G1_BH + brow[np] + col);
            #pragma unroll
            for (int mt = 0; mt < 2; ++mt)
                #pragma unroll
                for (int nt = 0; nt < 8; ++nt)
                    mma_f16(c[mt][nt], ah[mt], bh[nt >> 1][nt & 1], bh[nt >> 1][(nt & 1) + 2]);
        }
    }

    // epilogue: add bias, store q16
    const int sID = blockIdx.x >> 2;
    const int aLoc0 = (blockIdx.x & 3) * 128;
    uint16_t* qh16 = q16 + (size_t)sID * F_DIM * N_ATOM;
    #pragma unroll
    for (int mt = 0; mt < 2; ++mt) {
        #pragma unroll
        for (int nt = 0; nt < 8; ++nt) {
            const int fg = fB + wm + mt * 16 + (lane >> 2);
            const int ag = aLoc0 + wn + nt * 8 + (lane & 3) * 2;
            float* cf = c[mt][nt];
            float bv0 = bias[fg], bv1 = bias[fg + 8];
            __half2 p01 = __floats2half2_rn(cf[0] + bv0, cf[1] + bv0);
            __half2 p23 = __floats2half2_rn(cf[2] + bv1, cf[3] + bv1);
            *(__half2*)(qh16 + (size_t)fg * N_ATOM + ag) = p01;
            *(__half2*)(qh16 + (size_t)(fg + 8) * N_ATOM + ag) = p23;
        }
    }
}

// ===========================================================================
// GEMM2 fused (R11 structure): out[s,m,f] = 0.5*(sum_j v(m,j) q[j,f])*q[m,f]
// v single fp16 on-the-fly (vectorized pos loads), q single fp16.
// BM=128, BN=256, BK=64. 512 threads, warp tile 32x64 (4m x 4n warps).
// 8 chunks, 1 sync each. V 2-stage, Q 3-stage.
// smem: pos@0(6K) | V @6144 (2 x 18432) | Q @43008 (3 x 36864) = 153600
// row stride 144B (128B data + 16B pad).
// ===========================================================================
#define G2_VS(st) (6144 + (st) * 18432)
#define G2_QS(st) (43008 + (st) * 36864)
#define G2_SMEM 153600

__device__ __forceinline__ void gemm2_step(
    uint32_t vbase, uint32_t qbase,
    const uint32_t arow[2], const uint32_t brow[4], float c[2][8][4])
{
    #pragma unroll
    for (int ks = 0; ks < 4; ++ks) {
        const uint32_t col = (uint32_t)(ks * 32);
        uint32_t ah[2][4], bh[4][4];
        #pragma unroll
        for (int mt = 0; mt < 2; ++mt) ldsm4(ah[mt], vbase + arow[mt] + col);
        #pragma unroll
        for (int np = 0; np < 4; ++np) ldsm4(bh[np], qbase + brow[np] + col);
        #pragma unroll
        for (int mt = 0; mt < 2; ++mt)
            #pragma unroll
            for (int nt = 0; nt < 8; ++nt)
                mma_f16(c[mt][nt], ah[mt], bh[nt >> 1][nt & 1], bh[nt >> 1][(nt & 1) + 2]);
    }
}

__global__ __launch_bounds__(512) void gemm2_fused(
    const float* __restrict__ pos,
    const uint16_t* __restrict__ q16,
    float* __restrict__ out)
{
    extern __shared__ char sm[];
    const int t = threadIdx.x, lane = t & 31, w = t >> 5;
    const int wm = (w & 3) * 32, wn = (w >> 2) * 64;
    const int m0 = blockIdx.x * 128, s = blockIdx.y;
    const uint32_t sb = smem_u32(sm);

    float* sx = (float*)(sm);
    float* sy = (float*)(sm + 2048);
    float* sz = (float*)(sm + 4096);

    // stage all positions of system s (512 threads -> 1 atom each)
    const float* ps = pos + (size_t)s * N_ATOM * 3;
    {
        float3 p = *(const float3*)(ps + t * 3);
        sx[t] = p.x; sy[t] = p.y; sz[t] = p.z;
    }
    __syncthreads();

    const int irow = t >> 2;            // 0..127 (v row)
    const int jq   = (t & 3);           // 16-j group within 64-chunk
    const int ig   = m0 + irow;
    const float xi = sx[ig], yi = sy[ig], zi = sz[ig];
    const float cc = 3.14159265358979323846f / R_EXCL;

    const char* Bq = (const char*)(q16 + (size_t)s * F_DIM * N_ATOM);  // 1024B row stride

    float c[2][8][4] = {};
    const int mrow = (lane & 7) + ((lane >> 3) & 1) * 8;
    const int kb   = (lane >> 4) * 16;
    uint32_t arow[2], brow[4];
    #pragma unroll
    for (int mt = 0; mt < 2; ++mt) arow[mt] = (uint32_t)((wm + mt * 16 + mrow) * 144 + kb);
    #pragma unroll
    for (int np = 0; np < 4; ++np) brow[np] = (uint32_t)((wn + np * 16 + mrow) * 144 + kb);

    // v producer: 16 evals with vectorized (float4) position loads
    auto produce_v = [&](int ch, int st) {
        const int jbase = ch * 64 + jq * 16;
        __half2 hq[8];
        #pragma unroll
        for (int p = 0; p < 4; ++p) {
            const int j0 = jbase + p * 4;
            float4 x4 = *(const float4*)(sx + j0);
            float4 y4 = *(const float4*)(sy + j0);
            float4 z4 = *(const float4*)(sz + j0);
            float vv[4];
            #pragma unroll
            for (int e = 0; e < 4; ++e) {
                float dx = xi - ((const float*)&x4)[e];
                float dy = yi - ((const float*)&y4)[e];
                float dz = zi - ((const float*)&z4)[e];
                float d2 = fmaf(dx, dx, fmaf(dy, dy, dz * dz));
                float val = 0.0f;
                if (j0 + e != ig) {
                    float inv = rsqrtf(d2);
                    float d = d2 * inv;
                    float fcut = (d < R_EXCL) ? 0.5f * (1.0f + __cosf(cc * d)) : 0.0f;
                    val = (1.0f - fcut) * inv;
                }
                vv[e] = val;
            }
            hq[p * 2]     = __floats2half2_rn(vv[0], vv[1]);
            hq[p * 2 + 1] = __floats2half2_rn(vv[2], vv[3]);
        }
        uint32_t off = (uint32_t)(G2_VS(st) + irow * 144 + jq * 32);
        *(uint4*)(sm + off)      = ((uint4*)hq)[0];
        *(uint4*)(sm + off + 16) = ((uint4*)hq)[1];
    };
    // q loader: 256 rows x 128B per chunk = 2048 x 16B, 4 per thread
    auto load_q = [&](int ch, int st) {
        #pragma unroll
        for (int j = 0; j < 4; ++j) {
            int u = t + j * 512;
            int row = u >> 3, sg = u & 7;
            const char* src = Bq + (size_t)row * 1024 + ch * 128 + sg * 16;
            CP_ASYNC16(sb + (uint32_t)(G2_QS(st) + row * 144 + sg * 16), src);
        }
        CP_COMMIT();
    };

    // prologue: v[0], q[0], q[1]
    produce_v(0, 0);
    load_q(0, 0);
    load_q(1, 1);

    for (int ch = 0; ch < 8; ++ch) {
        __syncthreads();   // prev-chunk MMA done -> reused v/q stages free
        if (ch + 1 < 8) produce_v(ch + 1, (ch + 1) & 1);
        if (ch + 2 < 8) {
            load_q(ch + 2, (ch + 2) % 3);
            CP_WAIT(2);
        } else if (ch + 1 < 8) {
            CP_WAIT(1);
        } else {
            CP_WAIT(0);
        }
        gemm2_step(sb + (uint32_t)G2_VS(ch & 1), sb + (uint32_t)G2_QS(ch % 3), arow, brow, c);
    }
    __syncthreads();

    // Epilogue: stage q16[m,f] tile as fp32 in 2 f-halves (smem stride 132)
    float* sq = (float*)sm;
    float* outB = out + ((size_t)(s * N_ATOM) + m0) * F_DIM;
    #pragma unroll
    for (int h = 0; h < 2; ++h) {
        #pragma unroll
        for (int j = 0; j < 8; ++j) {
            int u = t + j * 512;
            int row = u >> 5, un = u & 31;
            uint2 hr = *(const uint2*)(Bq + (size_t)(h * 128 + row) * 1024
                                       + (size_t)(m0 + un * 4) * 2);
            float2 f0 = __half22float2(*(__half2*)&hr.x);
            float2 f1 = __half22float2(*(__half2*)&hr.y);
            *(float4*)(sq + row * 132 + un * 4) = make_float4(f0.x, f0.y, f1.x, f1.y);
        }
        __syncthreads();
        if ((wn >> 7) == h) {
            #pragma unroll
            for (int mt = 0; mt < 2; ++mt) {
                #pragma unroll
                for (int nt = 0; nt < 8; ++nt) {
                    const int ml = wm + mt * 16 + (lane >> 2);
                    const int fg = wn + nt * 8 + (lane & 3) * 2;     // global f
                    const int fl = fg - h * 128;                     // local to half
                    float* cf = c[mt][nt];
                    float q00 = sq[fl * 132 + ml], q01 = sq[(fl + 1) * 132 + ml];
                    float2 o0 = make_float2(0.5f * cf[0] * q00, 0.5f * cf[1] * q01);
                    *(float2*)(outB + (size_t)ml * F_DIM + fg) = o0;
                    float q10 = sq[fl * 132 + ml + 8], q11 = sq[(fl + 1) * 132 + ml + 8];
                    float2 o1 = make_float2(0.5f * cf[2] * q10, 0.5f * cf[3] * q11);
                    *(float2*)(outB + (size_t)(ml + 8) * F_DIM + fg) = o1;
                }
            }
        }
        __syncthreads();
    }
}

// ---------------------------------------------------------------------------
extern "C" void kernel_launch(void* const* d_in, const int* in_sizes, int n_in,
                              void* d_out, int out_size)
{
    const float* positions = (const float*)d_in[0]; // [32, 512, 3]
    const float* features  = (const float*)d_in[1]; // [16384, 256]
    const float* W         = (const float*)d_in[2]; // [256, 256]
    const float* b         = (const float*)d_in[3]; // [256]
    float* out             = (float*)d_out;         // [16384, 256]

    uint16_t* q16;
    cudaGetSymbolAddress((void**)&q16, g_q16);

    cudaFuncSetAttribute(gemm1_mma, cudaFuncAttributeMaxDynamicSharedMemorySize, G1_SMEM);
    cudaFuncSetAttribute(gemm2_fused, cudaFuncAttributeMaxDynamicSharedMemorySize, G2_SMEM);

    // q^T = W @ feat^T + b  (single fp16), 256 CTAs
    gemm1_mma<<<dim3(128, 2), 256, G1_SMEM>>>(W, features, b, q16);
    // out = 0.5 * (v @ q) * q, v single fp16 generated in-kernel, 128 CTAs
    gemm2_fused<<<dim3(4, 32), 512, G2_SMEM>>>(positions, q16, out);
}